// round 1
// baseline (speedup 1.0000x reference)
#include <cuda_runtime.h>
#include <math.h>

// ---------------- Problem constants ----------------
#define JJ      4
#define BB      8192
#define HH      100       // H_ENC == H_DEC == EMB
#define G3      300       // 3*H
#define TT      10        // L_IN == L_OUT
#define VV      11
#define BT      16        // batch cols per block
#define ROWS    64        // JJ*BT
#define NTHREADS 512
#define NBLOCKS (BB/BT)   // 512

// ---------------- Device scratch (allocation-free rule: __device__ globals) ----------------
__device__ float g_H[(size_t)JJ*TT*BB*HH];   // [j][t][b][e], 131MB
__device__ float g_wenc[30300];              // WhhT[k*300+g] (k<100), bhh at 30000+g
__device__ float g_wdec[30300];
__device__ float g_att[30000];               // A_wT[f*100+e] (f<100), W_wT at 10000 + k*100+e (k<200)
__device__ float g_lut_enc[VV*G3];           // [v][g] = Wih[g][v] + bih[g]
__device__ float g_lut_dec[VV*G3];

// ---------------- Prep kernel: transpose weights, build one-hot LUTs ----------------
__global__ void prep_kernel(const float* __restrict__ eWih, const float* __restrict__ eWhh,
                            const float* __restrict__ ebih, const float* __restrict__ ebhh,
                            const float* __restrict__ dWih, const float* __restrict__ dWhh,
                            const float* __restrict__ dbih, const float* __restrict__ dbhh,
                            const float* __restrict__ Ww,   const float* __restrict__ Aw)
{
    int i = blockIdx.x * blockDim.x + threadIdx.x;
    if (i < 30000) {
        int k = i / G3, g = i % G3;
        g_wenc[i] = eWhh[g*HH + k];
        g_wdec[i] = dWhh[g*HH + k];
    } else if (i < 30300) {
        int g = i - 30000;
        g_wenc[i] = ebhh[g];
        g_wdec[i] = dbhh[g];
    }
    if (i < 10000) {            // A_wT[f][e] = A_w[e][f]
        int f = i / HH, e = i % HH;
        g_att[i] = Aw[e*HH + f];
    }
    if (i < 20000) {            // W_wT[k][e] = W_w[e][k], k<200
        int k = i / HH, e = i % HH;
        g_att[10000 + i] = Ww[e*200 + k];
    }
    if (i < VV*G3) {
        int v = i / G3, g = i % G3;
        g_lut_enc[i] = eWih[g*VV + v] + ebih[g];
        g_lut_dec[i] = dWih[g*VV + v] + dbih[g];
    }
}

// ---------------- smem layout (floats) ----------------
#define OFF_W     0         // 30300 : staged weights (WhhT+bhh | A_wT+W_wT)
#define OFF_B0    30300     // 64*101 ping-pong hidden / P
#define OFF_B1    36764     // 64*101 scratch / c
#define OFF_LUT   43228     // 3300
#define OFF_M     46528     // 16*101
#define OFF_SC    48144     // 64*10 scores/logs
#define OFF_VW    48784     // 1100
#define OFF_VB    49884     // 12
#define OFF_WB    49896     // 100
#define OFF_LG    49996     // 16*12 logits
#define OFF_TOK   50188     // 64 ints
#define OFF_SCORE 50252     // 16
#define SMEM_FLOATS 50268
#define SMEM_BYTES  (SMEM_FLOATS*4)

__device__ __forceinline__ float sigf(float x) { return 1.0f / (1.0f + __expf(-x)); }

// GRU step on 64 rows: gh = h@WhhT (+bhh), combine with LUT gi, write h' (and H).
__device__ __forceinline__ void gru_step(const float* __restrict__ s_w,
                                         const float* __restrict__ s_lut,
                                         const int*   __restrict__ s_tok,
                                         const float* __restrict__ s_hin,
                                         float*       __restrict__ s_hout,
                                         int ty, int tx, bool writeH, int t, int b0)
{
    float acc[4][3][4];
    #pragma unroll
    for (int i = 0; i < 4; i++)
        #pragma unroll
        for (int gte = 0; gte < 3; gte++)
            #pragma unroll
            for (int c = 0; c < 4; c++) acc[i][gte][c] = 0.f;

    #pragma unroll 2
    for (int k = 0; k < HH; k++) {
        float h[4];
        #pragma unroll
        for (int i = 0; i < 4; i++) h[i] = s_hin[(ty*4+i)*101 + k];
        const float* wr = s_w + k*G3;
        #pragma unroll
        for (int c = 0; c < 4; c++) {
            int g = tx + 32*c;            // g up to 127: in-bounds garbage, masked later
            float w0 = wr[g], w1 = wr[100+g], w2 = wr[200+g];
            #pragma unroll
            for (int i = 0; i < 4; i++) {
                acc[i][0][c] = fmaf(h[i], w0, acc[i][0][c]);
                acc[i][1][c] = fmaf(h[i], w1, acc[i][1][c]);
                acc[i][2][c] = fmaf(h[i], w2, acc[i][2][c]);
            }
        }
    }
    #pragma unroll
    for (int i = 0; i < 4; i++) {
        int r = ty*4 + i;
        const float* lut = s_lut + s_tok[r]*G3;
        #pragma unroll
        for (int c = 0; c < 4; c++) {
            int g = tx + 32*c;
            if (g < HH) {
                float hr = acc[i][0][c] + s_w[30000+g];
                float hz = acc[i][1][c] + s_w[30100+g];
                float hn = acc[i][2][c] + s_w[30200+g];
                float rg = sigf(lut[g]       + hr);
                float zg = sigf(lut[100+g]   + hz);
                float ng = tanhf(lut[200+g] + rg*hn);
                float hp = s_hin[r*101 + g];
                float hv = ng + zg*(hp - ng);
                s_hout[r*101 + g] = hv;
                if (writeH) {
                    int j = r >> 4, bi = r & 15;
                    g_H[(((size_t)(j*TT + t))*BB + (b0 + bi))*HH + g] = hv;
                }
            }
        }
    }
}

__global__ void __launch_bounds__(NTHREADS, 1)
robustfill_kernel(const int* __restrict__ inputs, const int* __restrict__ target,
                  const float* __restrict__ Vw, const float* __restrict__ Vb,
                  const float* __restrict__ Wb, float* __restrict__ out)
{
    extern __shared__ float sm[];
    float* s_w    = sm + OFF_W;
    float* s_b0   = sm + OFF_B0;
    float* s_b1   = sm + OFF_B1;
    float* s_lut  = sm + OFF_LUT;
    float* s_m    = sm + OFF_M;
    float* s_sc   = sm + OFF_SC;
    float* s_vw   = sm + OFF_VW;
    float* s_vb   = sm + OFF_VB;
    float* s_wb   = sm + OFF_WB;
    float* s_lg   = sm + OFF_LG;
    int*   s_tok  = (int*)(sm + OFF_TOK);
    float* s_scr  = sm + OFF_SCORE;

    const int tid = threadIdx.x;
    const int ty = tid >> 5, tx = tid & 31;
    const int b0 = blockIdx.x * BT;

    // ---- initial staging ----
    for (int i = tid; i < 30300; i += NTHREADS) s_w[i] = g_wenc[i];
    for (int i = tid; i < VV*G3; i += NTHREADS) s_lut[i] = g_lut_enc[i];
    for (int i = tid; i < VV*HH; i += NTHREADS) s_vw[i] = Vw[i];
    for (int i = tid; i < HH;    i += NTHREADS) s_wb[i] = Wb[i];
    if (tid < VV) s_vb[tid] = Vb[tid];
    if (tid < BT) s_scr[tid] = 0.f;
    for (int i = tid; i < ROWS*101; i += NTHREADS) s_b0[i] = 0.f;  // h0 = 0
    __syncthreads();

    float* hcur = s_b0;
    float* hnx  = s_b1;

    // ================= ENCODER =================
    for (int t = 0; t < TT; t++) {
        if (tid < ROWS) {
            int j = tid >> 4;
            s_tok[tid] = inputs[(j*TT + t)*BB + b0 + (tid & 15)];
        }
        __syncthreads();
        gru_step(s_w, s_lut, s_tok, hcur, hnx, ty, tx, true, t, b0);
        __syncthreads();
        float* tmp = hcur; hcur = hnx; hnx = tmp;
    }

    // ================= P0 = GRU(SOS, h_last) with decoder weights =================
    for (int i = tid; i < 30300; i += NTHREADS) s_w[i] = g_wdec[i];
    for (int i = tid; i < VV*G3; i += NTHREADS) s_lut[i] = g_lut_dec[i];
    if (tid < ROWS) s_tok[tid] = VV - 1;   // SOS one-hot index
    __syncthreads();
    gru_step(s_w, s_lut, s_tok, hcur, hnx, ty, tx, false, 0, b0);
    __syncthreads();
    { float* tmp = hcur; hcur = hnx; hnx = tmp; }   // hcur = P, hnx = scratch

    // ================= DECODER =================
    for (int t = 0; t < TT; t++) {
        // stage attention weights; load target tokens
        if (tid < ROWS) s_tok[tid] = target[t*BB + b0 + (tid & 15)];
        for (int i = tid; i < 30000; i += NTHREADS) s_w[i] = g_att[i];
        __syncthreads();

        // ---- D2: AP[r][e] = sum_f A_wT[f][e] * P[r][f]  -> hnx ----
        {
            float acc[4][4];
            #pragma unroll
            for (int i = 0; i < 4; i++)
                #pragma unroll
                for (int c = 0; c < 4; c++) acc[i][c] = 0.f;
            #pragma unroll 2
            for (int k = 0; k < HH; k++) {
                float p[4];
                #pragma unroll
                for (int i = 0; i < 4; i++) p[i] = hcur[(ty*4+i)*101 + k];
                const float* wr = s_w + k*HH;
                #pragma unroll
                for (int c = 0; c < 4; c++) {
                    float w = wr[tx + 32*c];
                    #pragma unroll
                    for (int i = 0; i < 4; i++) acc[i][c] = fmaf(p[i], w, acc[i][c]);
                }
            }
            #pragma unroll
            for (int i = 0; i < 4; i++)
                #pragma unroll
                for (int c = 0; c < 4; c++) {
                    int e = tx + 32*c;
                    if (e < HH) hnx[(ty*4+i)*101 + e] = acc[i][c];
                }
        }
        __syncthreads();

        // ---- D3: scores[r][tt] = sum_e H[j,tt,b,e] * AP[r][e] ----
        for (int task = tid; task < ROWS*TT; task += NTHREADS) {
            int r = task / TT, ttq = task % TT;
            int j = r >> 4, b = b0 + (r & 15);
            const float4* Hp = (const float4*)(g_H + (((size_t)(j*TT + ttq))*BB + b)*HH);
            const float* ap = hnx + r*101;
            float s = 0.f;
            #pragma unroll
            for (int e4 = 0; e4 < 25; e4++) {
                float4 h4 = Hp[e4];
                s += h4.x*ap[e4*4] + h4.y*ap[e4*4+1] + h4.z*ap[e4*4+2] + h4.w*ap[e4*4+3];
            }
            s_sc[r*TT + ttq] = s;
        }
        __syncthreads();

        // ---- D4: log_softmax over tt (per row) ----
        if (tid < ROWS) {
            float mx = -1e30f;
            #pragma unroll
            for (int q = 0; q < TT; q++) mx = fmaxf(mx, s_sc[tid*TT + q]);
            float se = 0.f;
            #pragma unroll
            for (int q = 0; q < TT; q++) se += expf(s_sc[tid*TT + q] - mx);
            float lse = mx + logf(se);
            #pragma unroll
            for (int q = 0; q < TT; q++) s_sc[tid*TT + q] -= lse;
        }
        __syncthreads();

        // ---- D5: c[r][e] = sum_tt logs[r][tt] * H[j,tt,b,e]  (overwrite hnx) ----
        for (int task = tid; task < ROWS*25; task += NTHREADS) {
            int r = task / 25, e4 = task % 25;
            int j = r >> 4, b = b0 + (r & 15);
            float ax = 0.f, ay = 0.f, az = 0.f, aw = 0.f;
            #pragma unroll
            for (int q = 0; q < TT; q++) {
                float lg = s_sc[r*TT + q];
                float4 h4 = *(const float4*)(g_H + (((size_t)(j*TT + q))*BB + b)*HH + e4*4);
                ax = fmaf(lg, h4.x, ax); ay = fmaf(lg, h4.y, ay);
                az = fmaf(lg, h4.z, az); aw = fmaf(lg, h4.w, aw);
            }
            float* cp = hnx + r*101 + e4*4;
            cp[0] = ax; cp[1] = ay; cp[2] = az; cp[3] = aw;
        }
        __syncthreads();

        // ---- D6: fc = tanh(W_w @ [P, c] + W_b); m = max over j ----
        {
            float acc[4][4];
            #pragma unroll
            for (int i = 0; i < 4; i++)
                #pragma unroll
                for (int c = 0; c < 4; c++) acc[i][c] = 0.f;
            const float* wfc = s_w + 10000;
            #pragma unroll 2
            for (int k = 0; k < HH; k++) {            // P part
                float p[4];
                #pragma unroll
                for (int i = 0; i < 4; i++) p[i] = hcur[(ty*4+i)*101 + k];
                const float* wr = wfc + k*HH;
                #pragma unroll
                for (int c = 0; c < 4; c++) {
                    float w = wr[tx + 32*c];
                    #pragma unroll
                    for (int i = 0; i < 4; i++) acc[i][c] = fmaf(p[i], w, acc[i][c]);
                }
            }
            #pragma unroll 2
            for (int k = 0; k < HH; k++) {            // c part
                float p[4];
                #pragma unroll
                for (int i = 0; i < 4; i++) p[i] = hnx[(ty*4+i)*101 + k];
                const float* wr = wfc + (HH + k)*HH;
                #pragma unroll
                for (int c = 0; c < 4; c++) {
                    float w = wr[tx + 32*c];
                    #pragma unroll
                    for (int i = 0; i < 4; i++) acc[i][c] = fmaf(p[i], w, acc[i][c]);
                }
            }
            int myj = ty >> 2;
            for (int jj = 0; jj < JJ; jj++) {
                if (myj == jj) {
                    #pragma unroll
                    for (int i = 0; i < 4; i++)
                        #pragma unroll
                        for (int c = 0; c < 4; c++) {
                            int e = tx + 32*c;
                            if (e < HH) {
                                int bi = (ty & 3)*4 + i;
                                float v = tanhf(acc[i][c] + s_wb[e]);
                                if (jj == 0) s_m[bi*101 + e] = v;
                                else         s_m[bi*101 + e] = fmaxf(s_m[bi*101 + e], v);
                            }
                        }
                }
                __syncthreads();
            }
        }

        // ---- D7: logits + log_softmax + score ----
        if (tid < BT*VV) {
            int bi = tid / VV, v = tid % VV;
            float a = s_vb[v];
            const float* vr = s_vw + v*HH;
            const float* mr = s_m + bi*101;
            #pragma unroll 4
            for (int e = 0; e < HH; e++) a = fmaf(mr[e], vr[e], a);
            s_lg[bi*12 + v] = a;
        }
        __syncthreads();
        if (tid < BT) {
            float mx = -1e30f;
            #pragma unroll
            for (int v = 0; v < VV; v++) mx = fmaxf(mx, s_lg[tid*12 + v]);
            float se = 0.f;
            #pragma unroll
            for (int v = 0; v < VV; v++) se += expf(s_lg[tid*12 + v] - mx);
            float lse = mx + logf(se);
            int tg = s_tok[tid];                        // target token (same for all j)
            s_scr[tid] += s_lg[tid*12 + tg] - lse;
        }
        // ---- D8: restage decoder GRU weights ----
        for (int i = tid; i < 30300; i += NTHREADS) s_w[i] = g_wdec[i];
        __syncthreads();

        // ---- D9: P_new = GRU(target_onehot, c) ; write into hcur (P slot) ----
        gru_step(s_w, s_lut, s_tok, hnx, hcur, ty, tx, false, 0, b0);
        __syncthreads();
    }

    if (tid < BT) out[b0 + tid] = s_scr[tid];
}

// ---------------- Launch ----------------
extern "C" void kernel_launch(void* const* d_in, const int* in_sizes, int n_in,
                              void* d_out, int out_size)
{
    const int*   inputs  = (const int*)  d_in[0];
    const int*   target  = (const int*)  d_in[1];
    const float* eWih    = (const float*)d_in[2];
    const float* eWhh    = (const float*)d_in[3];
    const float* ebih    = (const float*)d_in[4];
    const float* ebhh    = (const float*)d_in[5];
    const float* dWih    = (const float*)d_in[6];
    const float* dWhh    = (const float*)d_in[7];
    const float* dbih    = (const float*)d_in[8];
    const float* dbhh    = (const float*)d_in[9];
    const float* Ww      = (const float*)d_in[10];
    const float* Wb      = (const float*)d_in[11];
    const float* Vw      = (const float*)d_in[12];
    const float* Vb      = (const float*)d_in[13];
    const float* Aw      = (const float*)d_in[14];
    float* out = (float*)d_out;

    static int smem_set = 0;
    if (!smem_set) {
        cudaFuncSetAttribute(robustfill_kernel,
                             cudaFuncAttributeMaxDynamicSharedMemorySize, SMEM_BYTES);
        smem_set = 1;
    }

    prep_kernel<<<(30300 + 255)/256, 256>>>(eWih, eWhh, ebih, ebhh,
                                            dWih, dWhh, dbih, dbhh, Ww, Aw);
    robustfill_kernel<<<NBLOCKS, NTHREADS, SMEM_BYTES>>>(inputs, target, Vw, Vb, Wb, out);
}

// round 2
// speedup vs baseline: 1.4211x; 1.4211x over previous
#include <cuda_runtime.h>
#include <stdint.h>

// ---------------- Problem constants ----------------
#define JJ      4
#define BB      8192
#define HH      100
#define TT      10
#define VV      11
#define BT      16
#define ROWS    64        // JJ*BT
#define NTHREADS 512
#define NBLOCKS (BB/BT)   // 512
#define STR     102       // hidden row stride (even -> float2 aligned)
#define GP      112       // padded cols per gate
#define WROW    336       // 3*GP
#define ATT_SZ  33600     // 100*112 (A_wT) + 200*112 (W_wT)

// ---------------- Device scratch ----------------
__device__ __align__(16) float g_H[(size_t)JJ*TT*BB*HH];   // [j][t][b][e]
__device__ __align__(16) float g_wenc[HH*WROW];
__device__ __align__(16) float g_wdec[HH*WROW];
__device__ __align__(16) float g_benc[WROW];
__device__ __align__(16) float g_bdec[WROW];
__device__ __align__(16) float g_lenc[VV*WROW];
__device__ __align__(16) float g_ldec[VV*WROW];
__device__ __align__(16) float g_attw[ATT_SZ];   // [0,11200): A_wT2 [f][112e]; [11200,33600): W_wT2 [k][112e]

// ---------------- Packed fp32x2 helpers ----------------
__device__ __forceinline__ float tanha(float x){
    float y; asm("tanh.approx.f32 %0, %1;" : "=f"(y) : "f"(x)); return y;
}
__device__ __forceinline__ float sigf(float x){
    return 0.5f * tanha(0.5f * x) + 0.5f;
}
__device__ __forceinline__ uint64_t pk2(float a){
    uint64_t r; asm("mov.b64 %0, {%1, %1};" : "=l"(r) : "f"(a)); return r;
}
__device__ __forceinline__ void upk(uint64_t v, float& a, float& b){
    asm("mov.b64 {%0, %1}, %2;" : "=f"(a), "=f"(b) : "l"(v));
}
__device__ __forceinline__ void ffma2(uint64_t& d, uint64_t a, uint64_t b){
    asm("fma.rn.f32x2 %0, %1, %2, %0;" : "+l"(d) : "l"(a), "l"(b));
}

// ---------------- Prep kernel ----------------
__global__ void prep_kernel(const float* __restrict__ eWih, const float* __restrict__ eWhh,
                            const float* __restrict__ ebih, const float* __restrict__ ebhh,
                            const float* __restrict__ dWih, const float* __restrict__ dWhh,
                            const float* __restrict__ dbih, const float* __restrict__ dbhh,
                            const float* __restrict__ Ww,   const float* __restrict__ Aw)
{
    int i = blockIdx.x * blockDim.x + threadIdx.x;
    if (i < HH*WROW) {                          // Whh^T, gate-padded [k][3*112]
        int k = i / WROW, rem = i % WROW, g = rem / GP, col = rem % GP;
        float we = 0.f, wd = 0.f;
        if (col < HH) { we = eWhh[(g*HH + col)*HH + k]; wd = dWhh[(g*HH + col)*HH + k]; }
        g_wenc[i] = we; g_wdec[i] = wd;
    }
    if (i < WROW) {                             // bhh padded
        int g = i / GP, col = i % GP;
        g_benc[i] = (col < HH) ? ebhh[g*HH + col] : 0.f;
        g_bdec[i] = (col < HH) ? dbhh[g*HH + col] : 0.f;
    }
    if (i < VV*WROW) {                          // one-hot LUT: Wih[:,v] + bih, padded
        int v = i / WROW, rem = i % WROW, g = rem / GP, col = rem % GP;
        float le = 0.f, ld = 0.f;
        if (col < HH) { int gc = g*HH + col; le = eWih[gc*VV + v] + ebih[gc]; ld = dWih[gc*VV + v] + dbih[gc]; }
        g_lenc[i] = le; g_ldec[i] = ld;
    }
    if (i < HH*GP) {                            // A_wT2[f][e]
        int f = i / GP, e = i % GP;
        g_attw[i] = (e < HH) ? Aw[e*HH + f] : 0.f;
    }
    if (i < 200*GP) {                           // W_wT2[k][e], k<200
        int k = i / GP, e = i % GP;
        g_attw[HH*GP + i] = (e < HH) ? Ww[e*200 + k] : 0.f;
    }
}

// ---------------- smem layout (floats) ----------------
#define OFF_W     0                    // 33600
#define OFF_B0    33600                // 6528
#define OFF_B1    40128                // 6528
#define OFF_LUT   46656                // 3696
#define OFF_M     50352                // 1632 (16*102)
#define OFF_SC    51984                // 640
#define OFF_VW    52624                // 1100
#define OFF_BIAS  53724                // 336
#define OFF_WB    54060                // 112
#define OFF_VB    54172                // 12
#define OFF_LG    54184                // 192
#define OFF_TOK   54376                // 64 ints
#define OFF_SCORE 54440                // 16
#define SMEM_FLOATS 54456
#define SMEM_BYTES (SMEM_FLOATS*4)     // 217824

__device__ __forceinline__ void copy4(float* dst, const float* src, int n4, int tid){
    float4* d = (float4*)dst; const float4* s = (const float4*)src;
    for (int i = tid; i < n4; i += NTHREADS) d[i] = s[i];
}

// GRU step on 64 rows with packed f32x2 FMA.
__device__ __forceinline__ void gru_step(const float* __restrict__ s_w,
                                         const float* __restrict__ s_bias,
                                         const float* __restrict__ s_lut,
                                         const int*   __restrict__ s_tok,
                                         const float* __restrict__ s_hin,
                                         float*       __restrict__ s_hout,
                                         int ty, int tx, bool writeH, int t, int b0)
{
    uint64_t acc[4][3][2];
    {   // init with bhh bias (pair at col = 2*tx + 64*p)
        const uint64_t* bb = (const uint64_t*)s_bias;
        #pragma unroll
        for (int g = 0; g < 3; g++)
            #pragma unroll
            for (int p = 0; p < 2; p++) {
                uint64_t b2 = bb[g*(GP/2) + tx + 32*p];
                #pragma unroll
                for (int i = 0; i < 4; i++) acc[i][g][p] = b2;
            }
    }
    #pragma unroll 2
    for (int k = 0; k < HH; k++) {
        uint64_t h2[4];
        #pragma unroll
        for (int i = 0; i < 4; i++) h2[i] = pk2(s_hin[(ty*4+i)*STR + k]);
        const uint64_t* wr = (const uint64_t*)(s_w + k*WROW);
        uint64_t w[3][2];
        #pragma unroll
        for (int g = 0; g < 3; g++)
            #pragma unroll
            for (int p = 0; p < 2; p++) w[g][p] = wr[g*(GP/2) + tx + 32*p];
        #pragma unroll
        for (int i = 0; i < 4; i++)
            #pragma unroll
            for (int g = 0; g < 3; g++)
                #pragma unroll
                for (int p = 0; p < 2; p++) ffma2(acc[i][g][p], h2[i], w[g][p]);
    }
    #pragma unroll
    for (int p = 0; p < 2; p++) {
        int col = 2*tx + 64*p;
        if (p == 0 || tx < 18) {
            #pragma unroll
            for (int i = 0; i < 4; i++) {
                int r = ty*4 + i;
                const float* lut = s_lut + s_tok[r]*WROW;
                float2 lr = *(const float2*)(lut + col);
                float2 lz = *(const float2*)(lut + GP + col);
                float2 ln = *(const float2*)(lut + 2*GP + col);
                float2 hp = *(const float2*)(s_hin + r*STR + col);
                float a0,a1,b0v,b1v,c0,c1;
                upk(acc[i][0][p], a0, a1);
                upk(acc[i][1][p], b0v, b1v);
                upk(acc[i][2][p], c0, c1);
                float rg0 = sigf(lr.x + a0),  rg1 = sigf(lr.y + a1);
                float zg0 = sigf(lz.x + b0v), zg1 = sigf(lz.y + b1v);
                float ng0 = tanha(ln.x + rg0*c0), ng1 = tanha(ln.y + rg1*c1);
                float h0 = ng0 + zg0*(hp.x - ng0);
                float h1 = ng1 + zg1*(hp.y - ng1);
                *(float2*)(s_hout + r*STR + col) = make_float2(h0, h1);
                if (writeH) {
                    int j = r >> 4, bi = r & 15;
                    *(float2*)(g_H + (((size_t)(j*TT + t))*BB + (b0 + bi))*HH + col) = make_float2(h0, h1);
                }
            }
        }
    }
}

__global__ void __launch_bounds__(NTHREADS, 1)
robustfill_kernel(const int* __restrict__ inputs, const int* __restrict__ target,
                  const float* __restrict__ Vw, const float* __restrict__ Vb,
                  const float* __restrict__ Wb, float* __restrict__ out)
{
    extern __shared__ float sm[];
    float* s_w    = sm + OFF_W;
    float* s_b0   = sm + OFF_B0;
    float* s_b1   = sm + OFF_B1;
    float* s_lut  = sm + OFF_LUT;
    float* s_m    = sm + OFF_M;
    float* s_sc   = sm + OFF_SC;
    float* s_vw   = sm + OFF_VW;
    float* s_bias = sm + OFF_BIAS;
    float* s_wb   = sm + OFF_WB;
    float* s_vb   = sm + OFF_VB;
    float* s_lg   = sm + OFF_LG;
    int*   s_tok  = (int*)(sm + OFF_TOK);
    float* s_scr  = sm + OFF_SCORE;

    const int tid = threadIdx.x;
    const int ty = tid >> 5, tx = tid & 31;
    const int b0 = blockIdx.x * BT;

    // ---- initial staging ----
    copy4(s_w,    g_wenc, HH*WROW/4, tid);
    copy4(s_lut,  g_lenc, VV*WROW/4, tid);
    copy4(s_bias, g_benc, WROW/4,    tid);
    for (int i = tid; i < VV*HH; i += NTHREADS) s_vw[i] = Vw[i];
    for (int i = tid; i < GP;    i += NTHREADS) s_wb[i] = (i < HH) ? Wb[i] : 0.f;
    if (tid < VV) s_vb[tid] = Vb[tid];
    if (tid < BT) s_scr[tid] = 0.f;
    for (int i = tid; i < ROWS*STR/2; i += NTHREADS) *(float2*)(s_b0 + 2*i) = make_float2(0.f, 0.f);
    __syncthreads();

    float* hcur = s_b0;
    float* hnx  = s_b1;

    // ================= ENCODER =================
    for (int t = 0; t < TT; t++) {
        if (tid < ROWS) s_tok[tid] = inputs[((tid >> 4)*TT + t)*BB + b0 + (tid & 15)];
        __syncthreads();
        gru_step(s_w, s_bias, s_lut, s_tok, hcur, hnx, ty, tx, true, t, b0);
        __syncthreads();
        float* tmp = hcur; hcur = hnx; hnx = tmp;
    }

    // ================= P0 with decoder weights =================
    copy4(s_w,    g_wdec, HH*WROW/4, tid);
    copy4(s_lut,  g_ldec, VV*WROW/4, tid);
    copy4(s_bias, g_bdec, WROW/4,    tid);
    if (tid < ROWS) s_tok[tid] = VV - 1;
    __syncthreads();
    gru_step(s_w, s_bias, s_lut, s_tok, hcur, hnx, ty, tx, false, 0, b0);
    __syncthreads();
    { float* tmp = hcur; hcur = hnx; hnx = tmp; }   // hcur = P

    // ================= DECODER =================
    for (int t = 0; t < TT; t++) {
        if (tid < ROWS) s_tok[tid] = target[t*BB + b0 + (tid & 15)];
        copy4(s_w, g_attw, ATT_SZ/4, tid);        // A_wT2 + W_wT2
        __syncthreads();

        // ---- D2: AP[r][e] = sum_f A_wT[f][e] * P[r][f] -> hnx ----
        {
            uint64_t acc[4][2];
            #pragma unroll
            for (int i = 0; i < 4; i++) { acc[i][0] = 0ull; acc[i][1] = 0ull; }
            #pragma unroll 2
            for (int f = 0; f < HH; f++) {
                uint64_t p2[4];
                #pragma unroll
                for (int i = 0; i < 4; i++) p2[i] = pk2(hcur[(ty*4+i)*STR + f]);
                const uint64_t* ar = (const uint64_t*)(s_w + f*GP);
                uint64_t w0 = ar[tx], w1 = ar[tx + 32];
                #pragma unroll
                for (int i = 0; i < 4; i++) { ffma2(acc[i][0], p2[i], w0); ffma2(acc[i][1], p2[i], w1); }
            }
            #pragma unroll
            for (int p = 0; p < 2; p++) {
                int col = 2*tx + 64*p;
                if (p == 0 || tx < 18) {
                    #pragma unroll
                    for (int i = 0; i < 4; i++) {
                        float a0, a1; upk(acc[i][p], a0, a1);
                        *(float2*)(hnx + (ty*4+i)*STR + col) = make_float2(a0, a1);
                    }
                }
            }
        }
        __syncthreads();

        // ---- D3: scores[r][q] = sum_e H[j,q,b,e] * AP[r][e] ----
        for (int task = tid; task < ROWS*TT; task += NTHREADS) {
            int r = task / TT, q = task % TT;
            int j = r >> 4, b = b0 + (r & 15);
            const float4* Hp = (const float4*)(g_H + (((size_t)(j*TT + q))*BB + b)*HH);
            const float* ap = hnx + r*STR;
            float s = 0.f;
            #pragma unroll
            for (int e4 = 0; e4 < 25; e4++) {
                float4 h4 = Hp[e4];
                s += h4.x*ap[e4*4] + h4.y*ap[e4*4+1] + h4.z*ap[e4*4+2] + h4.w*ap[e4*4+3];
            }
            s_sc[r*TT + q] = s;
        }
        __syncthreads();

        // ---- D4: log_softmax over q ----
        if (tid < ROWS) {
            float mx = -1e30f;
            #pragma unroll
            for (int q = 0; q < TT; q++) mx = fmaxf(mx, s_sc[tid*TT + q]);
            float se = 0.f;
            #pragma unroll
            for (int q = 0; q < TT; q++) se += __expf(s_sc[tid*TT + q] - mx);
            float lse = mx + __logf(se);
            #pragma unroll
            for (int q = 0; q < TT; q++) s_sc[tid*TT + q] -= lse;
        }
        __syncthreads();

        // ---- D5: c[r][e] = sum_q logs[r][q] * H[j,q,b,e] -> hnx ----
        for (int task = tid; task < ROWS*50; task += NTHREADS) {
            int r = task / 50, e2 = task % 50;
            int j = r >> 4, b = b0 + (r & 15);
            float ax = 0.f, ay = 0.f;
            #pragma unroll
            for (int q = 0; q < TT; q++) {
                float lg = s_sc[r*TT + q];
                float2 h2 = *(const float2*)(g_H + (((size_t)(j*TT + q))*BB + b)*HH + e2*2);
                ax = fmaf(lg, h2.x, ax); ay = fmaf(lg, h2.y, ay);
            }
            *(float2*)(hnx + r*STR + e2*2) = make_float2(ax, ay);
        }
        __syncthreads();

        // ---- D6: fc = tanh(W_w @ [P, c] + W_b); m = max over j ----
        {
            uint64_t acc[4][2];
            {
                const uint64_t* wbb = (const uint64_t*)s_wb;
                uint64_t w0 = wbb[tx], w1 = wbb[tx + 32];
                #pragma unroll
                for (int i = 0; i < 4; i++) { acc[i][0] = w0; acc[i][1] = w1; }
            }
            const float* wfc = s_w + HH*GP;       // W_wT2 region
            #pragma unroll 2
            for (int k = 0; k < HH; k++) {        // P part
                uint64_t p2[4];
                #pragma unroll
                for (int i = 0; i < 4; i++) p2[i] = pk2(hcur[(ty*4+i)*STR + k]);
                const uint64_t* wr = (const uint64_t*)(wfc + k*GP);
                uint64_t w0 = wr[tx], w1 = wr[tx + 32];
                #pragma unroll
                for (int i = 0; i < 4; i++) { ffma2(acc[i][0], p2[i], w0); ffma2(acc[i][1], p2[i], w1); }
            }
            #pragma unroll 2
            for (int k = 0; k < HH; k++) {        // c part
                uint64_t p2[4];
                #pragma unroll
                for (int i = 0; i < 4; i++) p2[i] = pk2(hnx[(ty*4+i)*STR + k]);
                const uint64_t* wr = (const uint64_t*)(wfc + (HH + k)*GP);
                uint64_t w0 = wr[tx], w1 = wr[tx + 32];
                #pragma unroll
                for (int i = 0; i < 4; i++) { ffma2(acc[i][0], p2[i], w0); ffma2(acc[i][1], p2[i], w1); }
            }
            int myj = ty >> 2;
            for (int jj = 0; jj < JJ; jj++) {
                if (myj == jj) {
                    #pragma unroll
                    for (int p = 0; p < 2; p++) {
                        int col = 2*tx + 64*p;
                        if (p == 0 || tx < 18) {
                            #pragma unroll
                            for (int i = 0; i < 4; i++) {
                                int bi = (ty & 3)*4 + i;
                                float f0, f1; upk(acc[i][p], f0, f1);
                                f0 = tanha(f0); f1 = tanha(f1);
                                float* mp = s_m + bi*STR + col;
                                if (jj == 0) { mp[0] = f0; mp[1] = f1; }
                                else { mp[0] = fmaxf(mp[0], f0); mp[1] = fmaxf(mp[1], f1); }
                            }
                        }
                    }
                }
                __syncthreads();
            }
        }

        // ---- D7: logits (overlap with dec-weight restage) ----
        if (tid < BT*VV) {
            int bi = tid / VV, v = tid % VV;
            float a = s_vb[v];
            const float2* mr = (const float2*)(s_m + bi*STR);
            const float2* vr = (const float2*)(s_vw + v*HH);
            #pragma unroll 5
            for (int e = 0; e < 50; e++) {
                float2 m2 = mr[e], v2 = vr[e];
                a = fmaf(m2.x, v2.x, fmaf(m2.y, v2.y, a));
            }
            s_lg[bi*12 + v] = a;
        }
        copy4(s_w, g_wdec, HH*WROW/4, tid);       // restage decoder GRU weights
        __syncthreads();

        // ---- score + D9: P_new = GRU(target_onehot, c) ----
        if (tid < BT) {
            float mx = -1e30f;
            #pragma unroll
            for (int v = 0; v < VV; v++) mx = fmaxf(mx, s_lg[tid*12 + v]);
            float se = 0.f;
            #pragma unroll
            for (int v = 0; v < VV; v++) se += __expf(s_lg[tid*12 + v] - mx);
            float lse = mx + __logf(se);
            s_scr[tid] += s_lg[tid*12 + s_tok[tid]] - lse;
        }
        gru_step(s_w, s_bias, s_lut, s_tok, hnx, hcur, ty, tx, false, 0, b0);
        __syncthreads();
    }

    if (tid < BT) out[b0 + tid] = s_scr[tid];
}

// ---------------- Launch ----------------
extern "C" void kernel_launch(void* const* d_in, const int* in_sizes, int n_in,
                              void* d_out, int out_size)
{
    const int*   inputs  = (const int*)  d_in[0];
    const int*   target  = (const int*)  d_in[1];
    const float* eWih    = (const float*)d_in[2];
    const float* eWhh    = (const float*)d_in[3];
    const float* ebih    = (const float*)d_in[4];
    const float* ebhh    = (const float*)d_in[5];
    const float* dWih    = (const float*)d_in[6];
    const float* dWhh    = (const float*)d_in[7];
    const float* dbih    = (const float*)d_in[8];
    const float* dbhh    = (const float*)d_in[9];
    const float* Ww      = (const float*)d_in[10];
    const float* Wb      = (const float*)d_in[11];
    const float* Vw      = (const float*)d_in[12];
    const float* Vb      = (const float*)d_in[13];
    const float* Aw      = (const float*)d_in[14];
    float* out = (float*)d_out;

    static int smem_set = 0;
    if (!smem_set) {
        cudaFuncSetAttribute(robustfill_kernel,
                             cudaFuncAttributeMaxDynamicSharedMemorySize, SMEM_BYTES);
        smem_set = 1;
    }

    prep_kernel<<<(HH*WROW + 255)/256, 256>>>(eWih, eWhh, ebih, ebhh,
                                              dWih, dWhh, dbih, dbhh, Ww, Aw);
    robustfill_kernel<<<NBLOCKS, NTHREADS, SMEM_BYTES>>>(inputs, target, Vw, Vb, Wb, out);
}

// round 3
// speedup vs baseline: 1.4633x; 1.0297x over previous
#include <cuda_runtime.h>
#include <stdint.h>

// ---------------- Problem constants ----------------
#define JJ      4
#define BB      8192
#define HH      100
#define TT      10
#define VV      11
#define BT      16
#define ROWS    64        // JJ*BT
#define NTHREADS 512
#define NBLOCKS (BB/BT)   // 512
#define STR     104       // hidden row stride (16B aligned rows)
#define WK      384       // interleaved weight floats per k (3 gates * 128)
#define WSZ     38400     // 100 * WK  (also = 12800 A_wT + 25600 W_wT)

// ---------------- Device scratch ----------------
__device__ __align__(16) float g_H[(size_t)JJ*TT*BB*HH];   // [j][t][b][e]
__device__ __align__(16) float g_wenc[WSZ];     // [k][g][lane tx]*4 : cols 4tx..4tx+3 (0 pad >=100)
__device__ __align__(16) float g_wdec[WSZ];
__device__ __align__(16) float g_attw[WSZ];     // [0,12800): A_wT [f][128]; [12800,38400): W_wT [k][128] k<200
__device__ __align__(16) float g_lenc[VV*300];  // [v][g*100+col] = Wih+bih (+bhh for r,z)
__device__ __align__(16) float g_ldec[VV*300];
__device__ __align__(16) float g_bnenc[128];    // bhh_n interleaved (col 4tx+c)
__device__ __align__(16) float g_bndec[128];
__device__ __align__(16) float g_wbi[128];      // W_b interleaved

// ---------------- helpers ----------------
__device__ __forceinline__ float tanha(float x){
    float y; asm("tanh.approx.f32 %0, %1;" : "=f"(y) : "f"(x)); return y;
}
__device__ __forceinline__ float sigf(float x){ return 0.5f * tanha(0.5f * x) + 0.5f; }
__device__ __forceinline__ uint64_t pk2(float a){
    uint64_t r; asm("mov.b64 %0, {%1, %1};" : "=l"(r) : "f"(a)); return r;
}
__device__ __forceinline__ void upk(uint64_t v, float& a, float& b){
    asm("mov.b64 {%0, %1}, %2;" : "=f"(a), "=f"(b) : "l"(v));
}
__device__ __forceinline__ void ffma2(uint64_t& d, uint64_t a, uint64_t b){
    asm("fma.rn.f32x2 %0, %1, %2, %0;" : "+l"(d) : "l"(a), "l"(b));
}
__device__ __forceinline__ float comp4(const float4& v, int u){
    return u==0 ? v.x : (u==1 ? v.y : (u==2 ? v.z : v.w));
}

// ---------------- Prep kernel ----------------
__global__ void prep_kernel(const float* __restrict__ eWih, const float* __restrict__ eWhh,
                            const float* __restrict__ ebih, const float* __restrict__ ebhh,
                            const float* __restrict__ dWih, const float* __restrict__ dWhh,
                            const float* __restrict__ dbih, const float* __restrict__ dbhh,
                            const float* __restrict__ Ww,   const float* __restrict__ Aw,
                            const float* __restrict__ Wb)
{
    int i = blockIdx.x * blockDim.x + threadIdx.x;
    if (i < WSZ) {                               // GRU Whh^T interleaved
        int k = i / WK, rem = i % WK, g = rem / 128, col = rem % 128;
        float we = 0.f, wd = 0.f;
        if (col < HH) {
            we = eWhh[(g*HH + col)*HH + k];
            wd = dWhh[(g*HH + col)*HH + k];
        }
        g_wenc[i] = we; g_wdec[i] = wd;
    }
    if (i < WSZ) {                               // attention weights
        float v = 0.f;
        if (i < 12800) {                         // A_wT [f][128]
            int f = i / 128, e = i % 128;
            if (e < HH) v = Aw[e*HH + f];
        } else {
            int i2 = i - 12800;                  // W_wT [k][128], k<200
            int k = i2 / 128, e = i2 % 128;
            if (e < HH) v = Ww[e*200 + k];
        }
        g_attw[i] = v;
    }
    if (i < VV*300) {                            // one-hot LUT (+bih, +bhh for r,z)
        int v = i / 300, rem = i % 300, g = rem / 100, col = rem % 100;
        int gc = g*HH + col;
        float extra_e = (g < 2) ? ebhh[gc] : 0.f;
        float extra_d = (g < 2) ? dbhh[gc] : 0.f;
        g_lenc[i] = eWih[gc*VV + v] + ebih[gc] + extra_e;
        g_ldec[i] = dWih[gc*VV + v] + dbih[gc] + extra_d;
    }
    if (i < 128) {
        g_bnenc[i] = (i < HH) ? ebhh[200 + i] : 0.f;
        g_bndec[i] = (i < HH) ? dbhh[200 + i] : 0.f;
        g_wbi[i]   = (i < HH) ? Wb[i] : 0.f;
    }
}

// ---------------- smem layout (floats) ----------------
#define OFF_W     0          // 38400
#define OFF_B0    38400      // 6656
#define OFF_B1    45056      // 6656
#define OFF_LUT   51712      // 3300
#define OFF_BN    55012      // 128
#define OFF_WBI   55140      // 128
#define OFF_M     55268      // 1664 (16*104)
#define OFF_SC    56932      // 640
#define OFF_VB    57572      // 12
#define OFF_LG    57584      // 192
#define OFF_TOK   57776      // 64 ints
#define OFF_SCORE 57840      // 16
#define SMEM_FLOATS 57856
#define SMEM_BYTES (SMEM_FLOATS*4)   // 231424

__device__ __forceinline__ void copy4(float* dst, const float* src, int n4, int tid){
    float4* d = (float4*)dst; const float4* s = (const float4*)src;
    for (int i = tid; i < n4; i += NTHREADS) d[i] = s[i];
}

// ---- GRU step on 64 rows: 3 LDS.128 weights/k, float4 h per 4k, prefetched ----
__device__ __forceinline__ void gru_step(const float* __restrict__ s_w,
                                         const float* __restrict__ s_bn,
                                         const float* __restrict__ s_lut,
                                         const int*   __restrict__ s_tok,
                                         const float* __restrict__ s_hin,
                                         float*       __restrict__ s_hout,
                                         int ty, int tx, bool writeH, int t, int b0)
{
    uint64_t acc[4][3][2];
    {
        ulonglong2 b = ((const ulonglong2*)s_bn)[tx];
        #pragma unroll
        for (int i = 0; i < 4; i++) {
            acc[i][0][0] = 0ull; acc[i][0][1] = 0ull;
            acc[i][1][0] = 0ull; acc[i][1][1] = 0ull;
            acc[i][2][0] = b.x;  acc[i][2][1] = b.y;
        }
    }
    const ulonglong2* wp = (const ulonglong2*)s_w;   // index (k*3+g)*32 + tx
    #pragma unroll 1
    for (int kk = 0; kk < HH; kk += 4) {
        float4 h4[4];
        #pragma unroll
        for (int i = 0; i < 4; i++) h4[i] = *(const float4*)(s_hin + (ty*4+i)*STR + kk);
        ulonglong2 w0 = wp[(kk*3+0)*32 + tx];
        ulonglong2 w1 = wp[(kk*3+1)*32 + tx];
        ulonglong2 w2 = wp[(kk*3+2)*32 + tx];
        #pragma unroll
        for (int u = 0; u < 4; u++) {
            ulonglong2 n0, n1, n2;
            if (u < 3) {
                n0 = wp[((kk+u+1)*3+0)*32 + tx];
                n1 = wp[((kk+u+1)*3+1)*32 + tx];
                n2 = wp[((kk+u+1)*3+2)*32 + tx];
            }
            #pragma unroll
            for (int i = 0; i < 4; i++) {
                uint64_t h2 = pk2(comp4(h4[i], u));
                ffma2(acc[i][0][0], h2, w0.x); ffma2(acc[i][0][1], h2, w0.y);
                ffma2(acc[i][1][0], h2, w1.x); ffma2(acc[i][1][1], h2, w1.y);
                ffma2(acc[i][2][0], h2, w2.x); ffma2(acc[i][2][1], h2, w2.y);
            }
            if (u < 3) { w0 = n0; w1 = n1; w2 = n2; }
        }
    }
    if (tx < 25) {
        #pragma unroll
        for (int i = 0; i < 4; i++) {
            int r = ty*4 + i;
            const float* lutb = s_lut + s_tok[r]*300;
            float4 lr = *(const float4*)(lutb +        4*tx);
            float4 lz = *(const float4*)(lutb + 100  + 4*tx);
            float4 ln = *(const float4*)(lutb + 200  + 4*tx);
            float4 hp = *(const float4*)(s_hin + r*STR + 4*tx);
            float a0,a1,a2,a3, b0v,b1v,b2v,b3v, c0,c1,c2,c3;
            upk(acc[i][0][0], a0, a1);  upk(acc[i][0][1], a2, a3);
            upk(acc[i][1][0], b0v, b1v); upk(acc[i][1][1], b2v, b3v);
            upk(acc[i][2][0], c0, c1);  upk(acc[i][2][1], c2, c3);
            float r0 = sigf(lr.x + a0), r1 = sigf(lr.y + a1), r2 = sigf(lr.z + a2), r3 = sigf(lr.w + a3);
            float z0 = sigf(lz.x + b0v), z1 = sigf(lz.y + b1v), z2 = sigf(lz.z + b2v), z3 = sigf(lz.w + b3v);
            float n0 = tanha(ln.x + r0*c0), n1 = tanha(ln.y + r1*c1);
            float n2 = tanha(ln.z + r2*c2), n3 = tanha(ln.w + r3*c3);
            float4 ho;
            ho.x = n0 + z0*(hp.x - n0);
            ho.y = n1 + z1*(hp.y - n1);
            ho.z = n2 + z2*(hp.z - n2);
            ho.w = n3 + z3*(hp.w - n3);
            *(float4*)(s_hout + r*STR + 4*tx) = ho;
            if (writeH) {
                int j = r >> 4, bi = r & 15;
                *(float4*)(g_H + (((size_t)(j*TT + t))*BB + (b0 + bi))*HH + 4*tx) = ho;
            }
        }
    }
}

// ---- generic 100-k GEMM slab: acc[4][2] += in_rows @ W (interleaved [k][128]) ----
__device__ __forceinline__ void gemm100(uint64_t acc[4][2],
                                        const float* __restrict__ s_in,
                                        const ulonglong2* __restrict__ wq,
                                        int ty, int tx)
{
    #pragma unroll 1
    for (int kk = 0; kk < HH; kk += 4) {
        float4 p4[4];
        #pragma unroll
        for (int i = 0; i < 4; i++) p4[i] = *(const float4*)(s_in + (ty*4+i)*STR + kk);
        ulonglong2 w = wq[kk*32 + tx];
        #pragma unroll
        for (int u = 0; u < 4; u++) {
            ulonglong2 n;
            if (u < 3) n = wq[(kk+u+1)*32 + tx];
            #pragma unroll
            for (int i = 0; i < 4; i++) {
                uint64_t h2 = pk2(comp4(p4[i], u));
                ffma2(acc[i][0], h2, w.x);
                ffma2(acc[i][1], h2, w.y);
            }
            if (u < 3) w = n;
        }
    }
}

__global__ void __launch_bounds__(NTHREADS, 1)
robustfill_kernel(const int* __restrict__ inputs, const int* __restrict__ target,
                  const float* __restrict__ Vw, const float* __restrict__ Vb,
                  float* __restrict__ out)
{
    extern __shared__ float sm[];
    float* s_w    = sm + OFF_W;
    float* s_b0   = sm + OFF_B0;
    float* s_b1   = sm + OFF_B1;
    float* s_lut  = sm + OFF_LUT;
    float* s_bn   = sm + OFF_BN;
    float* s_wbi  = sm + OFF_WBI;
    float* s_m    = sm + OFF_M;
    float* s_sc   = sm + OFF_SC;
    float* s_vb   = sm + OFF_VB;
    float* s_lg   = sm + OFF_LG;
    int*   s_tok  = (int*)(sm + OFF_TOK);
    float* s_scr  = sm + OFF_SCORE;

    const int tid = threadIdx.x;
    const int ty = tid >> 5, tx = tid & 31;
    const int b0 = blockIdx.x * BT;

    // ---- initial staging ----
    copy4(s_w,   g_wenc,  WSZ/4,    tid);
    copy4(s_lut, g_lenc,  VV*300/4, tid);
    copy4(s_bn,  g_bnenc, 32,       tid);
    copy4(s_wbi, g_wbi,   32,       tid);
    if (tid < VV) s_vb[tid] = Vb[tid];
    if (tid < BT) s_scr[tid] = 0.f;
    for (int i = tid; i < ROWS*STR/4; i += NTHREADS)
        *(float4*)(s_b0 + 4*i) = make_float4(0.f, 0.f, 0.f, 0.f);
    __syncthreads();

    float* hcur = s_b0;
    float* hnx  = s_b1;

    // ================= ENCODER =================
    for (int t = 0; t < TT; t++) {
        if (tid < ROWS) s_tok[tid] = inputs[((tid >> 4)*TT + t)*BB + b0 + (tid & 15)];
        __syncthreads();
        gru_step(s_w, s_bn, s_lut, s_tok, hcur, hnx, ty, tx, true, t, b0);
        __syncthreads();
        float* tmp = hcur; hcur = hnx; hnx = tmp;
    }

    // ================= P0 with decoder weights =================
    copy4(s_w,   g_wdec,  WSZ/4,    tid);
    copy4(s_lut, g_ldec,  VV*300/4, tid);
    copy4(s_bn,  g_bndec, 32,       tid);
    if (tid < ROWS) s_tok[tid] = VV - 1;
    __syncthreads();
    gru_step(s_w, s_bn, s_lut, s_tok, hcur, hnx, ty, tx, false, 0, b0);
    __syncthreads();
    { float* tmp = hcur; hcur = hnx; hnx = tmp; }   // hcur = P

    // ================= DECODER =================
    for (int t = 0; t < TT; t++) {
        if (tid < ROWS) s_tok[tid] = target[t*BB + b0 + (tid & 15)];
        copy4(s_w, g_attw, WSZ/4, tid);          // A_wT + W_wT interleaved
        __syncthreads();

        // ---- D2: AP[r][e] = sum_f A_wT[f][e] * P[r][f] -> hnx ----
        {
            uint64_t acc[4][2];
            #pragma unroll
            for (int i = 0; i < 4; i++) { acc[i][0] = 0ull; acc[i][1] = 0ull; }
            gemm100(acc, hcur, (const ulonglong2*)s_w, ty, tx);
            if (tx < 25) {
                #pragma unroll
                for (int i = 0; i < 4; i++) {
                    float a0,a1,a2,a3;
                    upk(acc[i][0], a0, a1); upk(acc[i][1], a2, a3);
                    *(float4*)(hnx + (ty*4+i)*STR + 4*tx) = make_float4(a0,a1,a2,a3);
                }
            }
        }
        __syncthreads();

        // ---- D3: scores[r][q] = sum_e H[j,q,b,e] * AP[r][e] ----
        for (int task = tid; task < ROWS*TT; task += NTHREADS) {
            int r = task / TT, q = task % TT;
            int j = r >> 4, b = b0 + (r & 15);
            const float4* Hp = (const float4*)(g_H + (((size_t)(j*TT + q))*BB + b)*HH);
            const float4* ap = (const float4*)(hnx + r*STR);
            float s = 0.f;
            #pragma unroll
            for (int e4 = 0; e4 < 25; e4++) {
                float4 h4 = Hp[e4], a4 = ap[e4];
                s += h4.x*a4.x + h4.y*a4.y + h4.z*a4.z + h4.w*a4.w;
            }
            s_sc[r*TT + q] = s;
        }
        __syncthreads();

        // ---- D4: log_softmax over q ----
        if (tid < ROWS) {
            float mx = -1e30f;
            #pragma unroll
            for (int q = 0; q < TT; q++) mx = fmaxf(mx, s_sc[tid*TT + q]);
            float se = 0.f;
            #pragma unroll
            for (int q = 0; q < TT; q++) se += __expf(s_sc[tid*TT + q] - mx);
            float lse = mx + __logf(se);
            #pragma unroll
            for (int q = 0; q < TT; q++) s_sc[tid*TT + q] -= lse;
        }
        __syncthreads();

        // ---- D5: c[r][e] = sum_q logs[r][q] * H[j,q,b,e] -> hnx ----
        for (int task = tid; task < ROWS*50; task += NTHREADS) {
            int r = task / 50, e2 = task % 50;
            int j = r >> 4, b = b0 + (r & 15);
            float ax = 0.f, ay = 0.f;
            #pragma unroll
            for (int q = 0; q < TT; q++) {
                float lg = s_sc[r*TT + q];
                float2 h2 = *(const float2*)(g_H + (((size_t)(j*TT + q))*BB + b)*HH + e2*2);
                ax = fmaf(lg, h2.x, ax); ay = fmaf(lg, h2.y, ay);
            }
            *(float2*)(hnx + r*STR + e2*2) = make_float2(ax, ay);
        }
        __syncthreads();

        // ---- D6: fc = tanh(W_w @ [P, c] + W_b); m = max over j ----
        {
            uint64_t acc[4][2];
            {
                ulonglong2 wb2 = ((const ulonglong2*)s_wbi)[tx];
                #pragma unroll
                for (int i = 0; i < 4; i++) { acc[i][0] = wb2.x; acc[i][1] = wb2.y; }
            }
            const ulonglong2* wq = (const ulonglong2*)(s_w + 12800);
            gemm100(acc, hcur, wq,             ty, tx);   // P part   (k 0..99)
            gemm100(acc, hnx,  wq + 100*32,    ty, tx);   // c part   (k 100..199)
            int myj = ty >> 2;
            for (int jj = 0; jj < JJ; jj++) {
                if (myj == jj && tx < 25) {
                    #pragma unroll
                    for (int i = 0; i < 4; i++) {
                        int bi = (ty & 3)*4 + i;
                        float f0,f1,f2,f3;
                        upk(acc[i][0], f0, f1); upk(acc[i][1], f2, f3);
                        f0 = tanha(f0); f1 = tanha(f1); f2 = tanha(f2); f3 = tanha(f3);
                        float* mp = s_m + bi*STR + 4*tx;
                        if (jj == 0) { mp[0]=f0; mp[1]=f1; mp[2]=f2; mp[3]=f3; }
                        else {
                            mp[0]=fmaxf(mp[0],f0); mp[1]=fmaxf(mp[1],f1);
                            mp[2]=fmaxf(mp[2],f2); mp[3]=fmaxf(mp[3],f3);
                        }
                    }
                }
                __syncthreads();
            }
        }

        // ---- D7: logits (V_w from global/L2); overlap dec-weight restage ----
        if (tid < BT*VV) {
            int bi = tid / VV, v = tid % VV;
            float a = s_vb[v];
            const float4* vr = (const float4*)(Vw + v*HH);
            const float4* mr = (const float4*)(s_m + bi*STR);
            #pragma unroll
            for (int e = 0; e < 25; e++) {
                float4 m4 = mr[e], v4 = vr[e];
                a = fmaf(m4.x, v4.x, fmaf(m4.y, v4.y, fmaf(m4.z, v4.z, fmaf(m4.w, v4.w, a))));
            }
            s_lg[bi*12 + v] = a;
        }
        copy4(s_w, g_wdec, WSZ/4, tid);          // restage decoder GRU weights
        __syncthreads();

        // ---- score + D9: P_new = GRU(target_onehot, c) ----
        if (tid < BT) {
            float mx = -1e30f;
            #pragma unroll
            for (int v = 0; v < VV; v++) mx = fmaxf(mx, s_lg[tid*12 + v]);
            float se = 0.f;
            #pragma unroll
            for (int v = 0; v < VV; v++) se += __expf(s_lg[tid*12 + v] - mx);
            float lse = mx + __logf(se);
            s_scr[tid] += s_lg[tid*12 + s_tok[tid]] - lse;
        }
        gru_step(s_w, s_bn, s_lut, s_tok, hnx, hcur, ty, tx, false, 0, b0);
        __syncthreads();
    }

    if (tid < BT) out[b0 + tid] = s_scr[tid];
}

// ---------------- Launch ----------------
extern "C" void kernel_launch(void* const* d_in, const int* in_sizes, int n_in,
                              void* d_out, int out_size)
{
    const int*   inputs  = (const int*)  d_in[0];
    const int*   target  = (const int*)  d_in[1];
    const float* eWih    = (const float*)d_in[2];
    const float* eWhh    = (const float*)d_in[3];
    const float* ebih    = (const float*)d_in[4];
    const float* ebhh    = (const float*)d_in[5];
    const float* dWih    = (const float*)d_in[6];
    const float* dWhh    = (const float*)d_in[7];
    const float* dbih    = (const float*)d_in[8];
    const float* dbhh    = (const float*)d_in[9];
    const float* Ww      = (const float*)d_in[10];
    const float* Wb      = (const float*)d_in[11];
    const float* Vw      = (const float*)d_in[12];
    const float* Vb      = (const float*)d_in[13];
    const float* Aw      = (const float*)d_in[14];
    float* out = (float*)d_out;

    static int smem_set = 0;
    if (!smem_set) {
        cudaFuncSetAttribute(robustfill_kernel,
                             cudaFuncAttributeMaxDynamicSharedMemorySize, SMEM_BYTES);
        smem_set = 1;
    }

    prep_kernel<<<(WSZ + 255)/256, 256>>>(eWih, eWhh, ebih, ebhh,
                                          dWih, dWhh, dbih, dbhh, Ww, Aw, Wb);
    robustfill_kernel<<<NBLOCKS, NTHREADS, SMEM_BYTES>>>(inputs, target, Vw, Vb, out);
}